// round 11
// baseline (speedup 1.0000x reference)
#include <cuda_runtime.h>
#include <cuda_fp16.h>
#include <cstdint>
#include <math.h>

#define Hh 4
#define Tt 1024
#define Dd 8192
#define SCALE 0.011048543456039806f  /* 1/sqrt(8192) */

// ---------------- scratch (static device arrays; no allocation) -------------
__device__ __half g_qh[(size_t)Hh * Tt * Dd];        // 64 MB  rope'd query fp16
__device__ __half g_vt[(size_t)Hh * Dd * Tt];        // 64 MB  V^T [h][d][s]
__device__ __half g_sh[(size_t)Hh * Tt * Tt];        // 8 MB   masked scores fp16
__device__ float  g_part[2][Hh][36][128 * 128];      // 18.9 MB gemm1 k-split partials

// ---------------- helpers (base-arch PTX only) ------------------------------
__device__ __forceinline__ uint32_t smem_u32(const void* p) {
    uint32_t a;
    asm("{ .reg .u64 t; cvta.to.shared.u64 t, %1; cvt.u32.u64 %0, t; }" : "=r"(a) : "l"(p));
    return a;
}
__device__ __forceinline__ void cp16(uint32_t dst, const void* src) {
    asm volatile("cp.async.cg.shared.global [%0], [%1], 16;" :: "r"(dst), "l"(src) : "memory");
}
#define CP_COMMIT asm volatile("cp.async.commit_group;" ::: "memory")
#define CP_WAIT1  asm volatile("cp.async.wait_group 1;" ::: "memory")

__device__ __forceinline__ void ldsm4(uint32_t& r0, uint32_t& r1, uint32_t& r2, uint32_t& r3,
                                      uint32_t a) {
    asm volatile("ldmatrix.sync.aligned.m8n8.x4.shared.b16 {%0,%1,%2,%3}, [%4];"
                 : "=r"(r0), "=r"(r1), "=r"(r2), "=r"(r3) : "r"(a));
}
__device__ __forceinline__ void mma16816(float* c,
                                         uint32_t a0, uint32_t a1, uint32_t a2, uint32_t a3,
                                         uint32_t b0, uint32_t b1) {
    asm volatile(
        "mma.sync.aligned.m16n8k16.row.col.f32.f16.f16.f32 "
        "{%0,%1,%2,%3},{%4,%5,%6,%7},{%8,%9},{%0,%1,%2,%3};"
        : "+f"(c[0]), "+f"(c[1]), "+f"(c[2]), "+f"(c[3])
        : "r"(a0), "r"(a1), "r"(a2), "r"(a3), "r"(b0), "r"(b1));
}

// 128B rows, XOR swizzle: conflict-free ldmatrix + cp.async
#define SWZ(row, cb) ((row) * 128 + ((cb) ^ (((row) & 7) << 4)))

// BK=64: operand tile = 128 rows x 128B = 16 KB
#define OPER_B   16384
#define STAGE    32768   /* A | B */
#define NST      3       /* 96 KB/CTA -> 2 CTA/SM */

// ---------------------------------------------------------------------------
// Kernel 1: bug-faithful ROPE -> fp16 (2 pairs per thread, float4 reads)
// ---------------------------------------------------------------------------
__global__ void rope_kernel(const float* __restrict__ q) {
    long idx = (long)blockIdx.x * 256 + threadIdx.x;   // 2^23 double-pair idx
    int m2  = (int)(idx & (Dd / 4 - 1));               // 0..2047
    int row = (int)(idx >> 11);                        // h*T + t
    int t = row & (Tt - 1);
    int h = row >> 10;

    const float* qrow = q + ((long)row << 13);
    float4 v = *(const float4*)(qrow + 4 * m2);

    int m0   = 2 * m2;
    int q2   = t & 1;
    int dsrc = (q2 << 12) + m0;
    int tsrc = ((h & 1) << 9) + (t >> 1);
    int h2   = h >> 1;
    const float* base = q + ((long)(2 * h2) << 23);
    float2 rA = *(const float2*)(base + (1L << 23) + (long)tsrc * Dd + dsrc); // j=0 src (negate)
    float2 rB = *(const float2*)(base + (long)tsrc * Dd + dsrc);              // j=1 src

    const float inv2pi = 0.15915494309189535f;
    float f0 = exp2f(-(float)m0 * (1.0f / 256.0f)) * inv2pi;
    float f1 = exp2f(-(float)(m0 + 1) * (1.0f / 256.0f)) * inv2pi;
    float p0 = fmodf((float)t * f0, 1.0f);
    float p1 = fmodf((float)t * f1, 1.0f);
    float c0 = cospif(2.0f * p0), s0 = sinpif(2.0f * p0);
    float c1 = cospif(2.0f * p1), s1 = sinpif(2.0f * p1);

    float o0 = v.x * c0 - rA.x * s0;
    float o1 = v.y * c0 + rB.x * s0;
    float o2 = v.z * c1 - rA.y * s1;
    float o3 = v.w * c1 + rB.y * s1;

    __half2 w0 = __halves2half2(__float2half_rn(o0), __float2half_rn(o1));
    __half2 w1 = __halves2half2(__float2half_rn(o2), __float2half_rn(o3));
    uint2 pk;
    pk.x = *(uint32_t*)&w0;
    pk.y = *(uint32_t*)&w1;
    *(uint2*)(g_qh + ((long)row << 13) + 4 * m2) = pk;
}

// ---------------------------------------------------------------------------
// Kernel 2: V transpose [h][s][d] fp32 -> V^T [h][d][s] fp16
// ---------------------------------------------------------------------------
__global__ __launch_bounds__(256) void transpose_v(const float* __restrict__ V) {
    __shared__ float tile[32][33];
    int h = blockIdx.z;
    int d0 = blockIdx.x * 32, s0 = blockIdx.y * 32;
    int lx = threadIdx.x & 31, ly = threadIdx.x >> 5;
    const float* src = V + ((long)h << 23);
#pragma unroll
    for (int r = 0; r < 4; r++)
        tile[ly + r * 8][lx] = src[(long)(s0 + ly + r * 8) * Dd + d0 + lx];
    __syncthreads();
    long ob = ((long)h << 23);
#pragma unroll
    for (int r = 0; r < 4; r++) {
        int d = d0 + ly + r * 8;
        g_vt[ob + (long)d * Tt + s0 + lx] = __float2half_rn(tile[lx][ly + r * 8]);
    }
}

// ---------------------------------------------------------------------------
// Shared GEMM core: CTA 128x128, 4 warps of 64x64, BK=64, 3-stage ring,
// register fragment double-buffering (load kb+1 frags under kb MMAs).
// ---------------------------------------------------------------------------
__device__ __forceinline__ void ld_tile64(uint32_t sbase, const __half* g, long ld, int tid) {
#pragma unroll
    for (int i = 0; i < 8; i++) {
        int cid = i * 128 + tid;            // 0..1023
        int row = cid >> 3;
        int seg = cid & 7;
        cp16(sbase + SWZ(row, seg << 4), g + (long)row * ld + seg * 8);
    }
}

__device__ __forceinline__ void gemm_run4(
    const __half* __restrict__ A, long lda,
    const __half* __restrict__ B, long ldb,
    int nch, uint32_t s0, int tid, float acc[4][8][4], bool mma_on)
{
    const int lane = tid & 31, wid = tid >> 5;
    const int wm = (wid & 1) * 64, wn = (wid >> 1) * 64;

    // prologue: NST-1 = 2 stages
#pragma unroll
    for (int s = 0; s < NST - 1; s++) {
        uint32_t sb = s0 + s * STAGE;
        ld_tile64(sb,          A + s * 64, lda, tid);
        ld_tile64(sb + OPER_B, B + s * 64, ldb, tid);
        CP_COMMIT;
    }

    const int arow = lane & 15;
    const int acb  = (lane >> 4) << 4;
    const int brow = (lane & 7) + ((lane >> 4) << 3);
    const int bcb  = ((lane >> 3) & 1) << 4;

    uint32_t af[2][4][4], bf[2][4][4];

    int st = 0;                 // slot of current compute chunk
    int pf = NST - 1;           // slot being prefetched (chunk kc + NST - 1)
    for (int kc = 0; kc < nch; kc++) {
        CP_WAIT1;               // tile kc resident
        __syncthreads();        // all warps done with slot pf (consumed at kc-1)

        // prefetch chunk kc+NST-1 into free slot pf, issued before compute
        int kn = kc + NST - 1;
        if (kn < nch) {
            uint32_t sbp = s0 + pf * STAGE;
            ld_tile64(sbp,          A + kn * 64, lda, tid);
            ld_tile64(sbp + OPER_B, B + kn * 64, ldb, tid);
        }
        CP_COMMIT;

        uint32_t sb = s0 + st * STAGE;
        if (mma_on) {
            // load kb=0 fragments into buffer 0
#pragma unroll
            for (int mb = 0; mb < 4; mb++)
                ldsm4(af[0][mb][0], af[0][mb][1], af[0][mb][2], af[0][mb][3],
                      sb + SWZ(wm + mb * 16 + arow, acb));
#pragma unroll
            for (int nb = 0; nb < 4; nb++)
                ldsm4(bf[0][nb][0], bf[0][nb][1], bf[0][nb][2], bf[0][nb][3],
                      sb + OPER_B + SWZ(wn + nb * 16 + brow, bcb));

#pragma unroll
            for (int kb = 0; kb < 4; kb++) {
                int cur = kb & 1, nxt = cur ^ 1;
                if (kb < 3) {
                    int cbk = (kb + 1) * 32;
#pragma unroll
                    for (int mb = 0; mb < 4; mb++)
                        ldsm4(af[nxt][mb][0], af[nxt][mb][1], af[nxt][mb][2], af[nxt][mb][3],
                              sb + SWZ(wm + mb * 16 + arow, cbk + acb));
#pragma unroll
                    for (int nb = 0; nb < 4; nb++)
                        ldsm4(bf[nxt][nb][0], bf[nxt][nb][1], bf[nxt][nb][2], bf[nxt][nb][3],
                              sb + OPER_B + SWZ(wn + nb * 16 + brow, cbk + bcb));
                }
#pragma unroll
                for (int nb = 0; nb < 4; nb++) {
#pragma unroll
                    for (int mb = 0; mb < 4; mb++) {
                        mma16816(acc[mb][2 * nb],
                                 af[cur][mb][0], af[cur][mb][1], af[cur][mb][2], af[cur][mb][3],
                                 bf[cur][nb][0], bf[cur][nb][1]);
                        mma16816(acc[mb][2 * nb + 1],
                                 af[cur][mb][0], af[cur][mb][1], af[cur][mb][2], af[cur][mb][3],
                                 bf[cur][nb][2], bf[cur][nb][3]);
                    }
                }
            }
        }
        st = (st == NST - 1) ? 0 : st + 1;
        pf = (pf == NST - 1) ? 0 : pf + 1;
    }
}

// ---------------------------------------------------------------------------
// Kernel 3: gemm1 k-split partials: part[ks] = Q[bi] @ Q[bj]^T over K half
// ---------------------------------------------------------------------------
__global__ __launch_bounds__(128, 2) void gemm1_partial() {
    extern __shared__ char dyn[];
    uint32_t s0 = smem_u32(dyn);
    int tid = threadIdx.x;
    int p  = blockIdx.x;   // 0..35 lower-tri tile
    int ks = blockIdx.y;   // k half
    int h  = blockIdx.z;
    int bi = 0;
    while ((bi + 1) * (bi + 2) / 2 <= p) ++bi;
    int bj = p - bi * (bi + 1) / 2;

    long qb = ((long)h << 23) + (long)ks * (Dd / 2);
    const __half* A = g_qh + qb + (long)bi * 128 * Dd;
    const __half* B = g_qh + qb + (long)bj * 128 * Dd;

    float acc[4][8][4];
#pragma unroll
    for (int a = 0; a < 4; a++)
#pragma unroll
        for (int b = 0; b < 8; b++)
#pragma unroll
            for (int c = 0; c < 4; c++) acc[a][b][c] = 0.f;

    const int lane = tid & 31, wid = tid >> 5;
    const int wm = (wid & 1) * 64, wn = (wid >> 1) * 64;
    bool mma_on = !(bi == bj && wn > wm);   // fully-masked quadrant of diag tile

    gemm_run4(A, Dd, B, Dd, Dd / 2 / 64, s0, tid, acc, mma_on);

    float* C = g_part[ks][h][p];
    int r0 = wm + (lane >> 2);
    int c0 = wn + (lane & 3) * 2;
#pragma unroll
    for (int mb = 0; mb < 4; mb++) {
#pragma unroll
        for (int nb = 0; nb < 8; nb++) {
            float* c = acc[mb][nb];
#pragma unroll
            for (int rh = 0; rh < 2; rh++) {
                int rr = r0 + mb * 16 + rh * 8;
                *(float2*)(C + rr * 128 + c0 + nb * 8) =
                    make_float2(c[rh * 2 + 0], c[rh * 2 + 1]);
            }
        }
    }
}

// ---------------------------------------------------------------------------
// Kernel 3b: merge partials -> masked scaled fp16 scores (8 slices per tile)
// ---------------------------------------------------------------------------
__global__ __launch_bounds__(256) void merge_scores() {
    int blk = blockIdx.x;          // 0..287 : tile p = blk>>3, slice = blk&7
    int p = blk >> 3;
    int sl = blk & 7;
    int h = blockIdx.y;
    int bi = 0;
    while ((bi + 1) * (bi + 2) / 2 <= p) ++bi;
    int bj = p - bi * (bi + 1) / 2;

    const float* P0 = g_part[0][h][p] + sl * 16 * 128;
    const float* P1 = g_part[1][h][p] + sl * 16 * 128;
    long hb = (long)h * Tt * Tt;
    int trow0 = bi * 128 + sl * 16;

#pragma unroll
    for (int e = 0; e < 4; e++) {
        int i2 = e * 256 + threadIdx.x;       // 0..1023 (pairs in 16x128 slice)
        int r = i2 >> 6;                      // 0..15
        int cpair = (i2 & 63) * 2;            // 0..126
        float2 a = *(const float2*)(P0 + r * 128 + cpair);
        float2 b = *(const float2*)(P1 + r * 128 + cpair);
        int t = trow0 + r;
        int s = bj * 128 + cpair;
        float v0 = (s     < t) ? (a.x + b.x) * SCALE : 0.f;
        float v1 = (s + 1 < t) ? (a.y + b.y) * SCALE : 0.f;
        *(__half2*)(g_sh + hb + (long)t * Tt + s) =
            __halves2half2(__float2half_rn(v0), __float2half_rn(v1));
    }
}

// ---------------------------------------------------------------------------
// Kernel 4: out = scores @ V  (causal K), 4-warp CTA, 2/SM
// ---------------------------------------------------------------------------
__global__ __launch_bounds__(128, 2) void gemm2_out(float* __restrict__ O) {
    extern __shared__ char dyn[];
    uint32_t s0 = smem_u32(dyn);
    int tid = threadIdx.x;
    int bn = blockIdx.x;          // d tile 0..63
    int bi = 7 - blockIdx.y;      // t tile, big-K first
    int h  = blockIdx.z;

    const __half* A = g_sh + (long)h * Tt * Tt + (long)bi * 128 * Tt;
    const __half* B = g_vt + ((long)h << 23) + (long)bn * 128 * Tt;

    float acc[4][8][4];
#pragma unroll
    for (int a = 0; a < 4; a++)
#pragma unroll
        for (int b = 0; b < 8; b++)
#pragma unroll
            for (int c = 0; c < 4; c++) acc[a][b][c] = 0.f;

    int nch = (bi + 1) * 2;   // K = (bi+1)*128, BK=64
    gemm_run4(A, Tt, B, Tt, nch, s0, tid, acc, true);

    const int lane = tid & 31, wid = tid >> 5;
    const int wm = (wid & 1) * 64, wn = (wid >> 1) * 64;
    int tr0 = bi * 128 + wm + (lane >> 2);
    int dc0 = bn * 128 + wn + (lane & 3) * 2;
    long hb = ((long)h << 23);
#pragma unroll
    for (int mb = 0; mb < 4; mb++) {
#pragma unroll
        for (int nb = 0; nb < 8; nb++) {
            int dc = dc0 + nb * 8;
            float* c = acc[mb][nb];
#pragma unroll
            for (int rh = 0; rh < 2; rh++) {
                int rr = tr0 + mb * 16 + rh * 8;
                *(float2*)(O + hb + (long)rr * Dd + dc) =
                    make_float2(c[rh * 2 + 0], c[rh * 2 + 1]);
            }
        }
    }
}

// ---------------------------------------------------------------------------
extern "C" void kernel_launch(void* const* d_in, const int* in_sizes, int n_in,
                              void* d_out, int out_size) {
    (void)in_sizes; (void)n_in; (void)out_size;
    const float* query = (const float*)d_in[0];
    const float* value = (const float*)d_in[1];
    float* out = (float*)d_out;

    const int SMEM_BYTES = NST * STAGE;   // 96 KB per CTA
    static cudaStream_t s_side = 0;
    static cudaEvent_t ev_fork = 0, ev_join = 0;
    static int init_done = 0;
    if (!init_done) {
        cudaFuncSetAttribute(gemm1_partial, cudaFuncAttributeMaxDynamicSharedMemorySize, SMEM_BYTES);
        cudaFuncSetAttribute(gemm2_out,     cudaFuncAttributeMaxDynamicSharedMemorySize, SMEM_BYTES);
        cudaStreamCreateWithFlags(&s_side, cudaStreamNonBlocking);
        cudaEventCreateWithFlags(&ev_fork, cudaEventDisableTiming);
        cudaEventCreateWithFlags(&ev_join, cudaEventDisableTiming);
        init_done = 1;
    }

    // fork: transpose_v runs on side stream, overlapping rope+gemm1+merge
    cudaEventRecord(ev_fork, 0);
    cudaStreamWaitEvent(s_side, ev_fork, 0);
    dim3 gt(Dd / 32, Tt / 32, Hh);
    transpose_v<<<gt, 256, 0, s_side>>>(value);
    cudaEventRecord(ev_join, s_side);

    rope_kernel<<<32768, 256>>>(query);

    dim3 g1(36, 2, Hh);
    gemm1_partial<<<g1, 128, SMEM_BYTES>>>();

    dim3 gm(288, Hh);
    merge_scores<<<gm, 256>>>();

    // join: gemm2 needs both scores (main) and V^T (side)
    cudaStreamWaitEvent(0, ev_join, 0);
    dim3 g2(Dd / 128, Tt / 128, Hh);
    gemm2_out<<<g2, 128, SMEM_BYTES>>>(out);
}

// round 12
// speedup vs baseline: 1.0196x; 1.0196x over previous
#include <cuda_runtime.h>
#include <cuda_fp16.h>
#include <cstdint>
#include <math.h>

#define Hh 4
#define Tt 1024
#define Dd 8192
#define SCALE 0.011048543456039806f  /* 1/sqrt(8192) */

// ---------------- scratch (static device arrays; no allocation) -------------
__device__ __half g_qh[(size_t)Hh * Tt * Dd];        // 64 MB  rope'd query fp16
__device__ __half g_vt[(size_t)Hh * Dd * Tt];        // 64 MB  V^T [h][d][s]
__device__ __half g_sh[(size_t)Hh * Tt * Tt];        // 8 MB   masked scores fp16
__device__ float  g_part[2][Hh][36][128 * 128];      // 18.9 MB gemm1 k-split partials

// ---------------- helpers (base-arch PTX only) ------------------------------
__device__ __forceinline__ uint32_t smem_u32(const void* p) {
    uint32_t a;
    asm("{ .reg .u64 t; cvta.to.shared.u64 t, %1; cvt.u32.u64 %0, t; }" : "=r"(a) : "l"(p));
    return a;
}
__device__ __forceinline__ void cp16(uint32_t dst, const void* src) {
    asm volatile("cp.async.cg.shared.global [%0], [%1], 16;" :: "r"(dst), "l"(src) : "memory");
}
#define CP_COMMIT asm volatile("cp.async.commit_group;" ::: "memory")
#define CP_WAIT1  asm volatile("cp.async.wait_group 1;" ::: "memory")

__device__ __forceinline__ void ldsm4(uint32_t& r0, uint32_t& r1, uint32_t& r2, uint32_t& r3,
                                      uint32_t a) {
    asm volatile("ldmatrix.sync.aligned.m8n8.x4.shared.b16 {%0,%1,%2,%3}, [%4];"
                 : "=r"(r0), "=r"(r1), "=r"(r2), "=r"(r3) : "r"(a));
}
__device__ __forceinline__ void mma16816(float* c,
                                         uint32_t a0, uint32_t a1, uint32_t a2, uint32_t a3,
                                         uint32_t b0, uint32_t b1) {
    asm volatile(
        "mma.sync.aligned.m16n8k16.row.col.f32.f16.f16.f32 "
        "{%0,%1,%2,%3},{%4,%5,%6,%7},{%8,%9},{%0,%1,%2,%3};"
        : "+f"(c[0]), "+f"(c[1]), "+f"(c[2]), "+f"(c[3])
        : "r"(a0), "r"(a1), "r"(a2), "r"(a3), "r"(b0), "r"(b1));
}

// 128B rows, XOR swizzle: conflict-free ldmatrix + cp.async
#define SWZ(row, cb) ((row) * 128 + ((cb) ^ (((row) & 7) << 4)))

// BK=64: operand tile = 128 rows x 128B = 16 KB
#define OPER_B   16384
#define STAGE    32768   /* A | B */
#define NST      3       /* 96 KB/CTA -> 2 CTA/SM */

// ---------------------------------------------------------------------------
// Kernel 1: bug-faithful ROPE -> fp16 (per head; 2 pairs per thread)
// ---------------------------------------------------------------------------
__global__ void rope_kernel(const float* __restrict__ q, int h) {
    long idx = (long)blockIdx.x * 256 + threadIdx.x;   // 2^21 double-pairs per head
    int m2 = (int)(idx & (Dd / 4 - 1));                // 0..2047
    int t  = (int)(idx >> 11);                         // 0..1023
    int row = h * Tt + t;

    const float* qrow = q + ((long)row << 13);
    float4 v = *(const float4*)(qrow + 4 * m2);

    int m0   = 2 * m2;
    int q2   = t & 1;
    int dsrc = (q2 << 12) + m0;
    int tsrc = ((h & 1) << 9) + (t >> 1);
    int h2   = h >> 1;
    const float* base = q + ((long)(2 * h2) << 23);
    float2 rA = *(const float2*)(base + (1L << 23) + (long)tsrc * Dd + dsrc); // j=0 src (negate)
    float2 rB = *(const float2*)(base + (long)tsrc * Dd + dsrc);              // j=1 src

    const float inv2pi = 0.15915494309189535f;
    float f0 = exp2f(-(float)m0 * (1.0f / 256.0f)) * inv2pi;
    float f1 = exp2f(-(float)(m0 + 1) * (1.0f / 256.0f)) * inv2pi;
    float p0 = fmodf((float)t * f0, 1.0f);
    float p1 = fmodf((float)t * f1, 1.0f);
    float c0 = cospif(2.0f * p0), s0 = sinpif(2.0f * p0);
    float c1 = cospif(2.0f * p1), s1 = sinpif(2.0f * p1);

    float o0 = v.x * c0 - rA.x * s0;
    float o1 = v.y * c0 + rB.x * s0;
    float o2 = v.z * c1 - rA.y * s1;
    float o3 = v.w * c1 + rB.y * s1;

    __half2 w0 = __halves2half2(__float2half_rn(o0), __float2half_rn(o1));
    __half2 w1 = __halves2half2(__float2half_rn(o2), __float2half_rn(o3));
    uint2 pk;
    pk.x = *(uint32_t*)&w0;
    pk.y = *(uint32_t*)&w1;
    *(uint2*)(g_qh + ((long)row << 13) + 4 * m2) = pk;
}

// ---------------------------------------------------------------------------
// Kernel 2: V transpose (per head) [s][d] fp32 -> V^T [d][s] fp16
// ---------------------------------------------------------------------------
__global__ __launch_bounds__(256) void transpose_v(const float* __restrict__ V, int h) {
    __shared__ float tile[32][33];
    int d0 = blockIdx.x * 32, s0 = blockIdx.y * 32;
    int lx = threadIdx.x & 31, ly = threadIdx.x >> 5;
    const float* src = V + ((long)h << 23);
#pragma unroll
    for (int r = 0; r < 4; r++)
        tile[ly + r * 8][lx] = src[(long)(s0 + ly + r * 8) * Dd + d0 + lx];
    __syncthreads();
    long ob = ((long)h << 23);
#pragma unroll
    for (int r = 0; r < 4; r++) {
        int d = d0 + ly + r * 8;
        g_vt[ob + (long)d * Tt + s0 + lx] = __float2half_rn(tile[lx][ly + r * 8]);
    }
}

// ---------------------------------------------------------------------------
// Shared GEMM core: CTA 128x128, 4 warps of 64x64, BK=64, 3-stage ring,
// register fragment double-buffering.
// ---------------------------------------------------------------------------
__device__ __forceinline__ void ld_tile64(uint32_t sbase, const __half* g, long ld, int tid) {
#pragma unroll
    for (int i = 0; i < 8; i++) {
        int cid = i * 128 + tid;            // 0..1023
        int row = cid >> 3;
        int seg = cid & 7;
        cp16(sbase + SWZ(row, seg << 4), g + (long)row * ld + seg * 8);
    }
}

__device__ __forceinline__ void gemm_run4(
    const __half* __restrict__ A, long lda,
    const __half* __restrict__ B, long ldb,
    int nch, uint32_t s0, int tid, float acc[4][8][4], bool mma_on)
{
    const int lane = tid & 31, wid = tid >> 5;
    const int wm = (wid & 1) * 64, wn = (wid >> 1) * 64;

#pragma unroll
    for (int s = 0; s < NST - 1; s++) {
        uint32_t sb = s0 + s * STAGE;
        ld_tile64(sb,          A + s * 64, lda, tid);
        ld_tile64(sb + OPER_B, B + s * 64, ldb, tid);
        CP_COMMIT;
    }

    const int arow = lane & 15;
    const int acb  = (lane >> 4) << 4;
    const int brow = (lane & 7) + ((lane >> 4) << 3);
    const int bcb  = ((lane >> 3) & 1) << 4;

    uint32_t af[2][4][4], bf[2][4][4];

    int st = 0, pf = NST - 1;
    for (int kc = 0; kc < nch; kc++) {
        CP_WAIT1;
        __syncthreads();

        int kn = kc + NST - 1;
        if (kn < nch) {
            uint32_t sbp = s0 + pf * STAGE;
            ld_tile64(sbp,          A + kn * 64, lda, tid);
            ld_tile64(sbp + OPER_B, B + kn * 64, ldb, tid);
        }
        CP_COMMIT;

        uint32_t sb = s0 + st * STAGE;
        if (mma_on) {
#pragma unroll
            for (int mb = 0; mb < 4; mb++)
                ldsm4(af[0][mb][0], af[0][mb][1], af[0][mb][2], af[0][mb][3],
                      sb + SWZ(wm + mb * 16 + arow, acb));
#pragma unroll
            for (int nb = 0; nb < 4; nb++)
                ldsm4(bf[0][nb][0], bf[0][nb][1], bf[0][nb][2], bf[0][nb][3],
                      sb + OPER_B + SWZ(wn + nb * 16 + brow, bcb));

#pragma unroll
            for (int kb = 0; kb < 4; kb++) {
                int cur = kb & 1, nxt = cur ^ 1;
                if (kb < 3) {
                    int cbk = (kb + 1) * 32;
#pragma unroll
                    for (int mb = 0; mb < 4; mb++)
                        ldsm4(af[nxt][mb][0], af[nxt][mb][1], af[nxt][mb][2], af[nxt][mb][3],
                              sb + SWZ(wm + mb * 16 + arow, cbk + acb));
#pragma unroll
                    for (int nb = 0; nb < 4; nb++)
                        ldsm4(bf[nxt][nb][0], bf[nxt][nb][1], bf[nxt][nb][2], bf[nxt][nb][3],
                              sb + OPER_B + SWZ(wn + nb * 16 + brow, cbk + bcb));
                }
#pragma unroll
                for (int nb = 0; nb < 4; nb++) {
#pragma unroll
                    for (int mb = 0; mb < 4; mb++) {
                        mma16816(acc[mb][2 * nb],
                                 af[cur][mb][0], af[cur][mb][1], af[cur][mb][2], af[cur][mb][3],
                                 bf[cur][nb][0], bf[cur][nb][1]);
                        mma16816(acc[mb][2 * nb + 1],
                                 af[cur][mb][0], af[cur][mb][1], af[cur][mb][2], af[cur][mb][3],
                                 bf[cur][nb][2], bf[cur][nb][3]);
                    }
                }
            }
        }
        st = (st == NST - 1) ? 0 : st + 1;
        pf = (pf == NST - 1) ? 0 : pf + 1;
    }
}

// ---------------------------------------------------------------------------
// Kernel 3: gemm1 k-split partials (per head)
// ---------------------------------------------------------------------------
__global__ __launch_bounds__(128, 2) void gemm1_partial(int h) {
    extern __shared__ char dyn[];
    uint32_t s0 = smem_u32(dyn);
    int tid = threadIdx.x;
    int p  = blockIdx.x;   // 0..35 lower-tri tile
    int ks = blockIdx.y;   // k half
    int bi = 0;
    while ((bi + 1) * (bi + 2) / 2 <= p) ++bi;
    int bj = p - bi * (bi + 1) / 2;

    long qb = ((long)h << 23) + (long)ks * (Dd / 2);
    const __half* A = g_qh + qb + (long)bi * 128 * Dd;
    const __half* B = g_qh + qb + (long)bj * 128 * Dd;

    float acc[4][8][4];
#pragma unroll
    for (int a = 0; a < 4; a++)
#pragma unroll
        for (int b = 0; b < 8; b++)
#pragma unroll
            for (int c = 0; c < 4; c++) acc[a][b][c] = 0.f;

    const int lane = tid & 31, wid = tid >> 5;
    const int wm = (wid & 1) * 64, wn = (wid >> 1) * 64;
    bool mma_on = !(bi == bj && wn > wm);

    gemm_run4(A, Dd, B, Dd, Dd / 2 / 64, s0, tid, acc, mma_on);

    float* C = g_part[ks][h][p];
    int r0 = wm + (lane >> 2);
    int c0 = wn + (lane & 3) * 2;
#pragma unroll
    for (int mb = 0; mb < 4; mb++) {
#pragma unroll
        for (int nb = 0; nb < 8; nb++) {
            float* c = acc[mb][nb];
#pragma unroll
            for (int rh = 0; rh < 2; rh++) {
                int rr = r0 + mb * 16 + rh * 8;
                *(float2*)(C + rr * 128 + c0 + nb * 8) =
                    make_float2(c[rh * 2 + 0], c[rh * 2 + 1]);
            }
        }
    }
}

// ---------------------------------------------------------------------------
// Kernel 3b: merge partials -> masked scaled fp16 scores (per head)
// ---------------------------------------------------------------------------
__global__ __launch_bounds__(256) void merge_scores(int h) {
    int blk = blockIdx.x;          // 0..287 : tile p = blk>>3, slice = blk&7
    int p = blk >> 3;
    int sl = blk & 7;
    int bi = 0;
    while ((bi + 1) * (bi + 2) / 2 <= p) ++bi;
    int bj = p - bi * (bi + 1) / 2;

    const float* P0 = g_part[0][h][p] + sl * 16 * 128;
    const float* P1 = g_part[1][h][p] + sl * 16 * 128;
    long hb = (long)h * Tt * Tt;
    int trow0 = bi * 128 + sl * 16;

#pragma unroll
    for (int e = 0; e < 4; e++) {
        int i2 = e * 256 + threadIdx.x;
        int r = i2 >> 6;
        int cpair = (i2 & 63) * 2;
        float2 a = *(const float2*)(P0 + r * 128 + cpair);
        float2 b = *(const float2*)(P1 + r * 128 + cpair);
        int t = trow0 + r;
        int s = bj * 128 + cpair;
        float v0 = (s     < t) ? (a.x + b.x) * SCALE : 0.f;
        float v1 = (s + 1 < t) ? (a.y + b.y) * SCALE : 0.f;
        *(__half2*)(g_sh + hb + (long)t * Tt + s) =
            __halves2half2(__float2half_rn(v0), __float2half_rn(v1));
    }
}

// ---------------------------------------------------------------------------
// Kernel 4: out = scores @ V (per head, causal K)
// ---------------------------------------------------------------------------
__global__ __launch_bounds__(128, 2) void gemm2_out(float* __restrict__ O, int h) {
    extern __shared__ char dyn[];
    uint32_t s0 = smem_u32(dyn);
    int tid = threadIdx.x;
    int bn = blockIdx.x;          // d tile 0..63
    int bi = 7 - blockIdx.y;      // t tile, big-K first

    const __half* A = g_sh + (long)h * Tt * Tt + (long)bi * 128 * Tt;
    const __half* B = g_vt + ((long)h << 23) + (long)bn * 128 * Tt;

    float acc[4][8][4];
#pragma unroll
    for (int a = 0; a < 4; a++)
#pragma unroll
        for (int b = 0; b < 8; b++)
#pragma unroll
            for (int c = 0; c < 4; c++) acc[a][b][c] = 0.f;

    int nch = (bi + 1) * 2;
    gemm_run4(A, Tt, B, Tt, nch, s0, tid, acc, true);

    const int lane = tid & 31, wid = tid >> 5;
    const int wm = (wid & 1) * 64, wn = (wid >> 1) * 64;
    int tr0 = bi * 128 + wm + (lane >> 2);
    int dc0 = bn * 128 + wn + (lane & 3) * 2;
    long hb = ((long)h << 23);
#pragma unroll
    for (int mb = 0; mb < 4; mb++) {
#pragma unroll
        for (int nb = 0; nb < 8; nb++) {
            int dc = dc0 + nb * 8;
            float* c = acc[mb][nb];
#pragma unroll
            for (int rh = 0; rh < 2; rh++) {
                int rr = tr0 + mb * 16 + rh * 8;
                *(float2*)(O + hb + (long)rr * Dd + dc) =
                    make_float2(c[rh * 2 + 0], c[rh * 2 + 1]);
            }
        }
    }
}

__global__ void noop_kernel() {}

// ---------------------------------------------------------------------------
extern "C" void kernel_launch(void* const* d_in, const int* in_sizes, int n_in,
                              void* d_out, int out_size) {
    (void)in_sizes; (void)n_in; (void)out_size;
    const float* query = (const float*)d_in[0];
    const float* value = (const float*)d_in[1];
    float* out = (float*)d_out;

    const int SMEM_BYTES = NST * STAGE;   // 96 KB per CTA
    static cudaStream_t s_side[3] = {0, 0, 0};
    static cudaEvent_t ev_fork = 0;
    static cudaEvent_t ev_join[3] = {0, 0, 0};
    static int init_done = 0;
    if (!init_done) {
        cudaFuncSetAttribute(gemm1_partial, cudaFuncAttributeMaxDynamicSharedMemorySize, SMEM_BYTES);
        cudaFuncSetAttribute(gemm2_out,     cudaFuncAttributeMaxDynamicSharedMemorySize, SMEM_BYTES);
        for (int i = 0; i < 3; i++) {
            cudaStreamCreateWithFlags(&s_side[i], cudaStreamNonBlocking);
            cudaEventCreateWithFlags(&ev_join[i], cudaEventDisableTiming);
        }
        cudaEventCreateWithFlags(&ev_fork, cudaEventDisableTiming);
        init_done = 1;
    }

    // fork side streams off the main (capture) stream
    cudaEventRecord(ev_fork, 0);
    for (int i = 0; i < 3; i++)
        cudaStreamWaitEvent(s_side[i], ev_fork, 0);

    dim3 gt(Dd / 32, Tt / 32);
    dim3 g1(36, 2);
    dim3 g2(Dd / 128, Tt / 128);

    // per-head pipelines: head 0 on main stream, heads 1-3 on side streams
    for (int h = 0; h < Hh; h++) {
        cudaStream_t st = (h == 0) ? (cudaStream_t)0 : s_side[h - 1];
        rope_kernel<<<8192, 256, 0, st>>>(query, h);
        transpose_v<<<gt, 256, 0, st>>>(value, h);
        gemm1_partial<<<g1, 128, SMEM_BYTES, st>>>(h);
        merge_scores<<<288, 256, 0, st>>>(h);
        gemm2_out<<<g2, 128, SMEM_BYTES, st>>>(out, h);
    }

    // join side streams back into the main stream
    for (int i = 0; i < 3; i++) {
        cudaEventRecord(ev_join[i], s_side[i]);
        cudaStreamWaitEvent(0, ev_join[i], 0);
    }
    noop_kernel<<<1, 1>>>();
}

// round 13
// speedup vs baseline: 1.0526x; 1.0324x over previous
#include <cuda_runtime.h>
#include <cuda_fp16.h>
#include <cstdint>
#include <math.h>

#define Hh 4
#define Tt 1024
#define Dd 8192
#define SCALE 0.011048543456039806f  /* 1/sqrt(8192) */

// ---------------- scratch (static device arrays; no allocation) -------------
__device__ __half g_qh[(size_t)Hh * Tt * Dd];        // 64 MB  rope'd query fp16
__device__ __half g_vt[(size_t)Hh * Dd * Tt];        // 64 MB  V^T [h][d][s]
__device__ __half g_sh[(size_t)Hh * Tt * Tt];        // 8 MB   masked scores fp16
__device__ float  g_part[2][Hh][36][128 * 128];      // 18.9 MB gemm1 k-split partials

// ---------------- helpers (base-arch PTX only) ------------------------------
__device__ __forceinline__ uint32_t smem_u32(const void* p) {
    uint32_t a;
    asm("{ .reg .u64 t; cvta.to.shared.u64 t, %1; cvt.u32.u64 %0, t; }" : "=r"(a) : "l"(p));
    return a;
}
__device__ __forceinline__ void cp16(uint32_t dst, const void* src) {
    asm volatile("cp.async.cg.shared.global [%0], [%1], 16;" :: "r"(dst), "l"(src) : "memory");
}
#define CP_COMMIT asm volatile("cp.async.commit_group;" ::: "memory")
#define CP_WAIT1  asm volatile("cp.async.wait_group 1;" ::: "memory")

__device__ __forceinline__ void ldsm4(uint32_t& r0, uint32_t& r1, uint32_t& r2, uint32_t& r3,
                                      uint32_t a) {
    asm volatile("ldmatrix.sync.aligned.m8n8.x4.shared.b16 {%0,%1,%2,%3}, [%4];"
                 : "=r"(r0), "=r"(r1), "=r"(r2), "=r"(r3) : "r"(a));
}
__device__ __forceinline__ void mma16816(float* c,
                                         uint32_t a0, uint32_t a1, uint32_t a2, uint32_t a3,
                                         uint32_t b0, uint32_t b1) {
    asm volatile(
        "mma.sync.aligned.m16n8k16.row.col.f32.f16.f16.f32 "
        "{%0,%1,%2,%3},{%4,%5,%6,%7},{%8,%9},{%0,%1,%2,%3};"
        : "+f"(c[0]), "+f"(c[1]), "+f"(c[2]), "+f"(c[3])
        : "r"(a0), "r"(a1), "r"(a2), "r"(a3), "r"(b0), "r"(b1));
}

// 128B rows, XOR swizzle: conflict-free ldmatrix + cp.async
#define SWZ(row, cb) ((row) * 128 + ((cb) ^ (((row) & 7) << 4)))

// BK=64: operand tile = 128 rows x 128B = 16 KB
#define OPER_B   16384
#define STAGE    32768   /* A | B */
#define NST      3       /* 96 KB/CTA -> 2 CTA/SM */

// ---------------------------------------------------------------------------
// Kernel 1: bug-faithful ROPE -> fp16 (per head; fast-math sincos)
// ---------------------------------------------------------------------------
__global__ void rope_kernel(const float* __restrict__ q, int h) {
    long idx = (long)blockIdx.x * 256 + threadIdx.x;   // 2^21 double-pairs per head
    int m2 = (int)(idx & (Dd / 4 - 1));                // 0..2047
    int t  = (int)(idx >> 11);                         // 0..1023
    int row = h * Tt + t;

    const float* qrow = q + ((long)row << 13);
    float4 v = *(const float4*)(qrow + 4 * m2);

    int m0   = 2 * m2;
    int q2   = t & 1;
    int dsrc = (q2 << 12) + m0;
    int tsrc = ((h & 1) << 9) + (t >> 1);
    int h2   = h >> 1;
    const float* base = q + ((long)(2 * h2) << 23);
    float2 rA = *(const float2*)(base + (1L << 23) + (long)tsrc * Dd + dsrc); // j=0 src (negate)
    float2 rB = *(const float2*)(base + (long)tsrc * Dd + dsrc);              // j=1 src

    const float inv2pi = 0.15915494309189535f;
    const float twopi  = 6.283185307179586f;
    float f0 = exp2f(-(float)m0 * (1.0f / 256.0f)) * inv2pi;
    float f1 = exp2f(-(float)(m0 + 1) * (1.0f / 256.0f)) * inv2pi;
    float x0 = (float)t * f0;
    float x1 = (float)t * f1;
    float p0 = x0 - floorf(x0);
    float p1 = x1 - floorf(x1);
    float s0, c0, s1, c1;
    __sincosf(twopi * p0, &s0, &c0);
    __sincosf(twopi * p1, &s1, &c1);

    float o0 = v.x * c0 - rA.x * s0;
    float o1 = v.y * c0 + rB.x * s0;
    float o2 = v.z * c1 - rA.y * s1;
    float o3 = v.w * c1 + rB.y * s1;

    __half2 w0 = __halves2half2(__float2half_rn(o0), __float2half_rn(o1));
    __half2 w1 = __halves2half2(__float2half_rn(o2), __float2half_rn(o3));
    uint2 pk;
    pk.x = *(uint32_t*)&w0;
    pk.y = *(uint32_t*)&w1;
    *(uint2*)(g_qh + ((long)row << 13) + 4 * m2) = pk;
}

// ---------------------------------------------------------------------------
// Kernel 2: V transpose (per head) [s][d] fp32 -> V^T [d][s] fp16
// ---------------------------------------------------------------------------
__global__ __launch_bounds__(256) void transpose_v(const float* __restrict__ V, int h) {
    __shared__ float tile[32][33];
    int d0 = blockIdx.x * 32, s0 = blockIdx.y * 32;
    int lx = threadIdx.x & 31, ly = threadIdx.x >> 5;
    const float* src = V + ((long)h << 23);
#pragma unroll
    for (int r = 0; r < 4; r++)
        tile[ly + r * 8][lx] = src[(long)(s0 + ly + r * 8) * Dd + d0 + lx];
    __syncthreads();
    long ob = ((long)h << 23);
#pragma unroll
    for (int r = 0; r < 4; r++) {
        int d = d0 + ly + r * 8;
        g_vt[ob + (long)d * Tt + s0 + lx] = __float2half_rn(tile[lx][ly + r * 8]);
    }
}

// ---------------------------------------------------------------------------
// Shared GEMM core: CTA 128x128, 4 warps of 64x64, BK=64, 3-stage ring,
// register fragment double-buffering. (Frozen config — measured best.)
// ---------------------------------------------------------------------------
__device__ __forceinline__ void ld_tile64(uint32_t sbase, const __half* g, long ld, int tid) {
#pragma unroll
    for (int i = 0; i < 8; i++) {
        int cid = i * 128 + tid;            // 0..1023
        int row = cid >> 3;
        int seg = cid & 7;
        cp16(sbase + SWZ(row, seg << 4), g + (long)row * ld + seg * 8);
    }
}

__device__ __forceinline__ void gemm_run4(
    const __half* __restrict__ A, long lda,
    const __half* __restrict__ B, long ldb,
    int nch, uint32_t s0, int tid, float acc[4][8][4], bool mma_on)
{
    const int lane = tid & 31, wid = tid >> 5;
    const int wm = (wid & 1) * 64, wn = (wid >> 1) * 64;

#pragma unroll
    for (int s = 0; s < NST - 1; s++) {
        uint32_t sb = s0 + s * STAGE;
        ld_tile64(sb,          A + s * 64, lda, tid);
        ld_tile64(sb + OPER_B, B + s * 64, ldb, tid);
        CP_COMMIT;
    }

    const int arow = lane & 15;
    const int acb  = (lane >> 4) << 4;
    const int brow = (lane & 7) + ((lane >> 4) << 3);
    const int bcb  = ((lane >> 3) & 1) << 4;

    uint32_t af[2][4][4], bf[2][4][4];

    int st = 0, pf = NST - 1;
    for (int kc = 0; kc < nch; kc++) {
        CP_WAIT1;
        __syncthreads();

        int kn = kc + NST - 1;
        if (kn < nch) {
            uint32_t sbp = s0 + pf * STAGE;
            ld_tile64(sbp,          A + kn * 64, lda, tid);
            ld_tile64(sbp + OPER_B, B + kn * 64, ldb, tid);
        }
        CP_COMMIT;

        uint32_t sb = s0 + st * STAGE;
        if (mma_on) {
#pragma unroll
            for (int mb = 0; mb < 4; mb++)
                ldsm4(af[0][mb][0], af[0][mb][1], af[0][mb][2], af[0][mb][3],
                      sb + SWZ(wm + mb * 16 + arow, acb));
#pragma unroll
            for (int nb = 0; nb < 4; nb++)
                ldsm4(bf[0][nb][0], bf[0][nb][1], bf[0][nb][2], bf[0][nb][3],
                      sb + OPER_B + SWZ(wn + nb * 16 + brow, bcb));

#pragma unroll
            for (int kb = 0; kb < 4; kb++) {
                int cur = kb & 1, nxt = cur ^ 1;
                if (kb < 3) {
                    int cbk = (kb + 1) * 32;
#pragma unroll
                    for (int mb = 0; mb < 4; mb++)
                        ldsm4(af[nxt][mb][0], af[nxt][mb][1], af[nxt][mb][2], af[nxt][mb][3],
                              sb + SWZ(wm + mb * 16 + arow, cbk + acb));
#pragma unroll
                    for (int nb = 0; nb < 4; nb++)
                        ldsm4(bf[nxt][nb][0], bf[nxt][nb][1], bf[nxt][nb][2], bf[nxt][nb][3],
                              sb + OPER_B + SWZ(wn + nb * 16 + brow, cbk + bcb));
                }
#pragma unroll
                for (int nb = 0; nb < 4; nb++) {
#pragma unroll
                    for (int mb = 0; mb < 4; mb++) {
                        mma16816(acc[mb][2 * nb],
                                 af[cur][mb][0], af[cur][mb][1], af[cur][mb][2], af[cur][mb][3],
                                 bf[cur][nb][0], bf[cur][nb][1]);
                        mma16816(acc[mb][2 * nb + 1],
                                 af[cur][mb][0], af[cur][mb][1], af[cur][mb][2], af[cur][mb][3],
                                 bf[cur][nb][2], bf[cur][nb][3]);
                    }
                }
            }
        }
        st = (st == NST - 1) ? 0 : st + 1;
        pf = (pf == NST - 1) ? 0 : pf + 1;
    }
}

// ---------------------------------------------------------------------------
// Kernel 3: gemm1 k-split partials (per head)
// ---------------------------------------------------------------------------
__global__ __launch_bounds__(128, 2) void gemm1_partial(int h) {
    extern __shared__ char dyn[];
    uint32_t s0 = smem_u32(dyn);
    int tid = threadIdx.x;
    int p  = blockIdx.x;   // 0..35 lower-tri tile
    int ks = blockIdx.y;   // k half
    int bi = 0;
    while ((bi + 1) * (bi + 2) / 2 <= p) ++bi;
    int bj = p - bi * (bi + 1) / 2;

    long qb = ((long)h << 23) + (long)ks * (Dd / 2);
    const __half* A = g_qh + qb + (long)bi * 128 * Dd;
    const __half* B = g_qh + qb + (long)bj * 128 * Dd;

    float acc[4][8][4];
#pragma unroll
    for (int a = 0; a < 4; a++)
#pragma unroll
        for (int b = 0; b < 8; b++)
#pragma unroll
            for (int c = 0; c < 4; c++) acc[a][b][c] = 0.f;

    const int lane = tid & 31, wid = tid >> 5;
    const int wm = (wid & 1) * 64, wn = (wid >> 1) * 64;
    bool mma_on = !(bi == bj && wn > wm);

    gemm_run4(A, Dd, B, Dd, Dd / 2 / 64, s0, tid, acc, mma_on);

    float* C = g_part[ks][h][p];
    int r0 = wm + (lane >> 2);
    int c0 = wn + (lane & 3) * 2;
#pragma unroll
    for (int mb = 0; mb < 4; mb++) {
#pragma unroll
        for (int nb = 0; nb < 8; nb++) {
            float* c = acc[mb][nb];
#pragma unroll
            for (int rh = 0; rh < 2; rh++) {
                int rr = r0 + mb * 16 + rh * 8;
                *(float2*)(C + rr * 128 + c0 + nb * 8) =
                    make_float2(c[rh * 2 + 0], c[rh * 2 + 1]);
            }
        }
    }
}

// ---------------------------------------------------------------------------
// Kernel 3b: merge partials -> masked scaled fp16 scores (per head)
// ---------------------------------------------------------------------------
__global__ __launch_bounds__(256) void merge_scores(int h) {
    int blk = blockIdx.x;          // 0..287 : tile p = blk>>3, slice = blk&7
    int p = blk >> 3;
    int sl = blk & 7;
    int bi = 0;
    while ((bi + 1) * (bi + 2) / 2 <= p) ++bi;
    int bj = p - bi * (bi + 1) / 2;

    const float* P0 = g_part[0][h][p] + sl * 16 * 128;
    const float* P1 = g_part[1][h][p] + sl * 16 * 128;
    long hb = (long)h * Tt * Tt;
    int trow0 = bi * 128 + sl * 16;

#pragma unroll
    for (int e = 0; e < 4; e++) {
        int i2 = e * 256 + threadIdx.x;
        int r = i2 >> 6;
        int cpair = (i2 & 63) * 2;
        float2 a = *(const float2*)(P0 + r * 128 + cpair);
        float2 b = *(const float2*)(P1 + r * 128 + cpair);
        int t = trow0 + r;
        int s = bj * 128 + cpair;
        float v0 = (s     < t) ? (a.x + b.x) * SCALE : 0.f;
        float v1 = (s + 1 < t) ? (a.y + b.y) * SCALE : 0.f;
        *(__half2*)(g_sh + hb + (long)t * Tt + s) =
            __halves2half2(__float2half_rn(v0), __float2half_rn(v1));
    }
}

// ---------------------------------------------------------------------------
// Kernel 4: out = scores @ V (per head, causal K)
// ---------------------------------------------------------------------------
__global__ __launch_bounds__(128, 2) void gemm2_out(float* __restrict__ O, int h) {
    extern __shared__ char dyn[];
    uint32_t s0 = smem_u32(dyn);
    int tid = threadIdx.x;
    int bn = blockIdx.x;          // d tile 0..63
    int bi = 7 - blockIdx.y;      // t tile, big-K first

    const __half* A = g_sh + (long)h * Tt * Tt + (long)bi * 128 * Tt;
    const __half* B = g_vt + ((long)h << 23) + (long)bn * 128 * Tt;

    float acc[4][8][4];
#pragma unroll
    for (int a = 0; a < 4; a++)
#pragma unroll
        for (int b = 0; b < 8; b++)
#pragma unroll
            for (int c = 0; c < 4; c++) acc[a][b][c] = 0.f;

    int nch = (bi + 1) * 2;
    gemm_run4(A, Tt, B, Tt, nch, s0, tid, acc, true);

    const int lane = tid & 31, wid = tid >> 5;
    const int wm = (wid & 1) * 64, wn = (wid >> 1) * 64;
    int tr0 = bi * 128 + wm + (lane >> 2);
    int dc0 = bn * 128 + wn + (lane & 3) * 2;
    long hb = ((long)h << 23);
#pragma unroll
    for (int mb = 0; mb < 4; mb++) {
#pragma unroll
        for (int nb = 0; nb < 8; nb++) {
            int dc = dc0 + nb * 8;
            float* c = acc[mb][nb];
#pragma unroll
            for (int rh = 0; rh < 2; rh++) {
                int rr = tr0 + mb * 16 + rh * 8;
                *(float2*)(O + hb + (long)rr * Dd + dc) =
                    make_float2(c[rh * 2 + 0], c[rh * 2 + 1]);
            }
        }
    }
}

__global__ void noop_kernel() {}

// ---------------------------------------------------------------------------
extern "C" void kernel_launch(void* const* d_in, const int* in_sizes, int n_in,
                              void* d_out, int out_size) {
    (void)in_sizes; (void)n_in; (void)out_size;
    const float* query = (const float*)d_in[0];
    const float* value = (const float*)d_in[1];
    float* out = (float*)d_out;

    const int SMEM_BYTES = NST * STAGE;   // 96 KB per CTA
    static cudaStream_t s_side[3] = {0, 0, 0};
    static cudaEvent_t ev_fork = 0;
    static cudaEvent_t ev_join[3] = {0, 0, 0};
    static int init_done = 0;
    if (!init_done) {
        cudaFuncSetAttribute(gemm1_partial, cudaFuncAttributeMaxDynamicSharedMemorySize, SMEM_BYTES);
        cudaFuncSetAttribute(gemm2_out,     cudaFuncAttributeMaxDynamicSharedMemorySize, SMEM_BYTES);
        for (int i = 0; i < 3; i++) {
            cudaStreamCreateWithFlags(&s_side[i], cudaStreamNonBlocking);
            cudaEventCreateWithFlags(&ev_join[i], cudaEventDisableTiming);
        }
        cudaEventCreateWithFlags(&ev_fork, cudaEventDisableTiming);
        init_done = 1;
    }

    // fork side streams off the main (capture) stream
    cudaEventRecord(ev_fork, 0);
    for (int i = 0; i < 3; i++)
        cudaStreamWaitEvent(s_side[i], ev_fork, 0);

    dim3 gt(Dd / 32, Tt / 32);
    dim3 g1(36, 2);
    dim3 g2(Dd / 128, Tt / 128);

    // per-head pipelines: head 0 on main stream, heads 1-3 on side streams
    for (int h = 0; h < Hh; h++) {
        cudaStream_t st = (h == 0) ? (cudaStream_t)0 : s_side[h - 1];
        rope_kernel<<<8192, 256, 0, st>>>(query, h);
        transpose_v<<<gt, 256, 0, st>>>(value, h);
        gemm1_partial<<<g1, 128, SMEM_BYTES, st>>>(h);
        merge_scores<<<288, 256, 0, st>>>(h);
        gemm2_out<<<g2, 128, SMEM_BYTES, st>>>(out, h);
    }

    // join side streams back into the main stream
    for (int i = 0; i < 3; i++) {
        cudaEventRecord(ev_join[i], s_side[i]);
        cudaStreamWaitEvent(0, ev_join[i], 0);
    }
    noop_kernel<<<1, 1>>>();
}

// round 14
// speedup vs baseline: 1.0725x; 1.0189x over previous
#include <cuda_runtime.h>
#include <cuda_fp16.h>
#include <cstdint>
#include <math.h>

#define Hh 4
#define Tt 1024
#define Dd 8192
#define SCALE 0.011048543456039806f  /* 1/sqrt(8192) */

// ---------------- scratch (static device arrays; no allocation) -------------
__device__ __half g_qh[(size_t)Hh * Tt * Dd];        // 64 MB  rope'd query fp16
__device__ __half g_vt[(size_t)Hh * Dd * Tt];        // 64 MB  V^T [h][d][s]
__device__ __half g_sh[(size_t)Hh * Tt * Tt];        // 8 MB   masked scores fp16
__device__ float  g_part[2][Hh][36][128 * 128];      // 18.9 MB gemm1 k-split partials

// ---------------- helpers (base-arch PTX only) ------------------------------
__device__ __forceinline__ uint32_t smem_u32(const void* p) {
    uint32_t a;
    asm("{ .reg .u64 t; cvta.to.shared.u64 t, %1; cvt.u32.u64 %0, t; }" : "=r"(a) : "l"(p));
    return a;
}
__device__ __forceinline__ void cp16(uint32_t dst, const void* src) {
    asm volatile("cp.async.cg.shared.global [%0], [%1], 16;" :: "r"(dst), "l"(src) : "memory");
}
#define CP_COMMIT asm volatile("cp.async.commit_group;" ::: "memory")
#define CP_WAIT1  asm volatile("cp.async.wait_group 1;" ::: "memory")

__device__ __forceinline__ void ldsm4(uint32_t& r0, uint32_t& r1, uint32_t& r2, uint32_t& r3,
                                      uint32_t a) {
    asm volatile("ldmatrix.sync.aligned.m8n8.x4.shared.b16 {%0,%1,%2,%3}, [%4];"
                 : "=r"(r0), "=r"(r1), "=r"(r2), "=r"(r3) : "r"(a));
}
__device__ __forceinline__ void mma16816(float* c,
                                         uint32_t a0, uint32_t a1, uint32_t a2, uint32_t a3,
                                         uint32_t b0, uint32_t b1) {
    asm volatile(
        "mma.sync.aligned.m16n8k16.row.col.f32.f16.f16.f32 "
        "{%0,%1,%2,%3},{%4,%5,%6,%7},{%8,%9},{%0,%1,%2,%3};"
        : "+f"(c[0]), "+f"(c[1]), "+f"(c[2]), "+f"(c[3])
        : "r"(a0), "r"(a1), "r"(a2), "r"(a3), "r"(b0), "r"(b1));
}

// 128B rows, XOR swizzle: conflict-free ldmatrix + cp.async
#define SWZ(row, cb) ((row) * 128 + ((cb) ^ (((row) & 7) << 4)))

// BK=64: operand tile = 128 rows x 128B = 16 KB
#define OPER_B   16384
#define STAGE    32768   /* A | B */
#define NST      3       /* 96 KB/CTA -> 2 CTA/SM */

// ---------------------------------------------------------------------------
// Kernel 1: bug-faithful ROPE -> fp16 (per head; 8 elems/thread, fast sincos)
// ---------------------------------------------------------------------------
__global__ void rope_kernel(const float* __restrict__ q, int h) {
    long idx = (long)blockIdx.x * 256 + threadIdx.x;   // 2^20 quad-pair idx/head
    int m4 = (int)(idx & (Dd / 8 - 1));                // 0..1023 (8-elem group)
    int t  = (int)(idx >> 10);                         // 0..1023
    int row = h * Tt + t;

    const float* qrow = q + ((long)row << 13);
    float4 v0 = *(const float4*)(qrow + 8 * m4);
    float4 v1 = *(const float4*)(qrow + 8 * m4 + 4);

    int m0   = 4 * m4;                                 // pair index base (4 pairs)
    int q2   = t & 1;
    int dsrc = (q2 << 12) + m0;
    int tsrc = ((h & 1) << 9) + (t >> 1);
    int h2   = h >> 1;
    const float* base = q + ((long)(2 * h2) << 23);
    float4 rA = *(const float4*)(base + (1L << 23) + (long)tsrc * Dd + dsrc); // j=0 src (negate)
    float4 rB = *(const float4*)(base + (long)tsrc * Dd + dsrc);              // j=1 src

    const float inv2pi = 0.15915494309189535f;
    const float twopi  = 6.283185307179586f;
    float tf = (float)t;
    float s[4], c[4];
#pragma unroll
    for (int i = 0; i < 4; i++) {
        float f = exp2f(-(float)(m0 + i) * (1.0f / 256.0f)) * inv2pi;
        float x = tf * f;
        float p = x - floorf(x);
        __sincosf(twopi * p, &s[i], &c[i]);
    }

    float o0 = v0.x * c[0] - rA.x * s[0];
    float o1 = v0.y * c[0] + rB.x * s[0];
    float o2 = v0.z * c[1] - rA.y * s[1];
    float o3 = v0.w * c[1] + rB.y * s[1];
    float o4 = v1.x * c[2] - rA.z * s[2];
    float o5 = v1.y * c[2] + rB.z * s[2];
    float o6 = v1.z * c[3] - rA.w * s[3];
    float o7 = v1.w * c[3] + rB.w * s[3];

    __half2 w0 = __halves2half2(__float2half_rn(o0), __float2half_rn(o1));
    __half2 w1 = __halves2half2(__float2half_rn(o2), __float2half_rn(o3));
    __half2 w2 = __halves2half2(__float2half_rn(o4), __float2half_rn(o5));
    __half2 w3 = __halves2half2(__float2half_rn(o6), __float2half_rn(o7));
    uint4 pk;
    pk.x = *(uint32_t*)&w0;
    pk.y = *(uint32_t*)&w1;
    pk.z = *(uint32_t*)&w2;
    pk.w = *(uint32_t*)&w3;
    *(uint4*)(g_qh + ((long)row << 13) + 8 * m4) = pk;
}

// ---------------------------------------------------------------------------
// Kernel 2: V transpose (per head) [s][d] fp32 -> V^T [d][s] fp16
// ---------------------------------------------------------------------------
__global__ __launch_bounds__(256) void transpose_v(const float* __restrict__ V, int h) {
    __shared__ float tile[32][33];
    int d0 = blockIdx.x * 32, s0 = blockIdx.y * 32;
    int lx = threadIdx.x & 31, ly = threadIdx.x >> 5;
    const float* src = V + ((long)h << 23);
#pragma unroll
    for (int r = 0; r < 4; r++)
        tile[ly + r * 8][lx] = src[(long)(s0 + ly + r * 8) * Dd + d0 + lx];
    __syncthreads();
    long ob = ((long)h << 23);
#pragma unroll
    for (int r = 0; r < 4; r++) {
        int d = d0 + ly + r * 8;
        g_vt[ob + (long)d * Tt + s0 + lx] = __float2half_rn(tile[lx][ly + r * 8]);
    }
}

// ---------------------------------------------------------------------------
// Shared GEMM core: CTA 128x128, 4 warps of 64x64, BK=64, 3-stage ring,
// register fragment double-buffering. b_region=OPER_B normally; 0 when the
// B tile is byte-identical to A (gemm1 diagonal tiles) -> B cp.async skipped.
// ---------------------------------------------------------------------------
__device__ __forceinline__ void ld_tile64(uint32_t sbase, const __half* g, long ld, int tid) {
#pragma unroll
    for (int i = 0; i < 8; i++) {
        int cid = i * 128 + tid;            // 0..1023
        int row = cid >> 3;
        int seg = cid & 7;
        cp16(sbase + SWZ(row, seg << 4), g + (long)row * ld + seg * 8);
    }
}

__device__ __forceinline__ void gemm_run4(
    const __half* __restrict__ A, long lda,
    const __half* __restrict__ B, long ldb,
    int nch, uint32_t s0, int tid, float acc[4][8][4], bool mma_on,
    uint32_t b_region)
{
    const int lane = tid & 31, wid = tid >> 5;
    const int wm = (wid & 1) * 64, wn = (wid >> 1) * 64;
    const bool load_b = (b_region != 0);

#pragma unroll
    for (int s = 0; s < NST - 1; s++) {
        uint32_t sb = s0 + s * STAGE;
        ld_tile64(sb, A + s * 64, lda, tid);
        if (load_b) ld_tile64(sb + OPER_B, B + s * 64, ldb, tid);
        CP_COMMIT;
    }

    const int arow = lane & 15;
    const int acb  = (lane >> 4) << 4;
    const int brow = (lane & 7) + ((lane >> 4) << 3);
    const int bcb  = ((lane >> 3) & 1) << 4;

    uint32_t af[2][4][4], bf[2][4][4];

    int st = 0, pf = NST - 1;
    for (int kc = 0; kc < nch; kc++) {
        CP_WAIT1;
        __syncthreads();

        int kn = kc + NST - 1;
        if (kn < nch) {
            uint32_t sbp = s0 + pf * STAGE;
            ld_tile64(sbp, A + kn * 64, lda, tid);
            if (load_b) ld_tile64(sbp + OPER_B, B + kn * 64, ldb, tid);
        }
        CP_COMMIT;

        uint32_t sb = s0 + st * STAGE;
        uint32_t sbB = sb + b_region;
        if (mma_on) {
#pragma unroll
            for (int mb = 0; mb < 4; mb++)
                ldsm4(af[0][mb][0], af[0][mb][1], af[0][mb][2], af[0][mb][3],
                      sb + SWZ(wm + mb * 16 + arow, acb));
#pragma unroll
            for (int nb = 0; nb < 4; nb++)
                ldsm4(bf[0][nb][0], bf[0][nb][1], bf[0][nb][2], bf[0][nb][3],
                      sbB + SWZ(wn + nb * 16 + brow, bcb));

#pragma unroll
            for (int kb = 0; kb < 4; kb++) {
                int cur = kb & 1, nxt = cur ^ 1;
                if (kb < 3) {
                    int cbk = (kb + 1) * 32;
#pragma unroll
                    for (int mb = 0; mb < 4; mb++)
                        ldsm4(af[nxt][mb][0], af[nxt][mb][1], af[nxt][mb][2], af[nxt][mb][3],
                              sb + SWZ(wm + mb * 16 + arow, cbk + acb));
#pragma unroll
                    for (int nb = 0; nb < 4; nb++)
                        ldsm4(bf[nxt][nb][0], bf[nxt][nb][1], bf[nxt][nb][2], bf[nxt][nb][3],
                              sbB + SWZ(wn + nb * 16 + brow, cbk + bcb));
                }
#pragma unroll
                for (int nb = 0; nb < 4; nb++) {
#pragma unroll
                    for (int mb = 0; mb < 4; mb++) {
                        mma16816(acc[mb][2 * nb],
                                 af[cur][mb][0], af[cur][mb][1], af[cur][mb][2], af[cur][mb][3],
                                 bf[cur][nb][0], bf[cur][nb][1]);
                        mma16816(acc[mb][2 * nb + 1],
                                 af[cur][mb][0], af[cur][mb][1], af[cur][mb][2], af[cur][mb][3],
                                 bf[cur][nb][2], bf[cur][nb][3]);
                    }
                }
            }
        }
        st = (st == NST - 1) ? 0 : st + 1;
        pf = (pf == NST - 1) ? 0 : pf + 1;
    }
}

// ---------------------------------------------------------------------------
// Kernel 3: gemm1 k-split partials (per head)
// ---------------------------------------------------------------------------
__global__ __launch_bounds__(128, 2) void gemm1_partial(int h) {
    extern __shared__ char dyn[];
    uint32_t s0 = smem_u32(dyn);
    int tid = threadIdx.x;
    int p  = blockIdx.x;   // 0..35 lower-tri tile
    int ks = blockIdx.y;   // k half
    int bi = 0;
    while ((bi + 1) * (bi + 2) / 2 <= p) ++bi;
    int bj = p - bi * (bi + 1) / 2;

    long qb = ((long)h << 23) + (long)ks * (Dd / 2);
    const __half* A = g_qh + qb + (long)bi * 128 * Dd;
    const __half* B = g_qh + qb + (long)bj * 128 * Dd;

    float acc[4][8][4];
#pragma unroll
    for (int a = 0; a < 4; a++)
#pragma unroll
        for (int b = 0; b < 8; b++)
#pragma unroll
            for (int c = 0; c < 4; c++) acc[a][b][c] = 0.f;

    const int lane = tid & 31, wid = tid >> 5;
    const int wm = (wid & 1) * 64, wn = (wid >> 1) * 64;
    bool mma_on = !(bi == bj && wn > wm);
    uint32_t b_region = (bi == bj) ? 0 : OPER_B;   // diag: B tile == A tile

    gemm_run4(A, Dd, B, Dd, Dd / 2 / 64, s0, tid, acc, mma_on, b_region);

    float* C = g_part[ks][h][p];
    int r0 = wm + (lane >> 2);
    int c0 = wn + (lane & 3) * 2;
#pragma unroll
    for (int mb = 0; mb < 4; mb++) {
#pragma unroll
        for (int nb = 0; nb < 8; nb++) {
            float* c = acc[mb][nb];
#pragma unroll
            for (int rh = 0; rh < 2; rh++) {
                int rr = r0 + mb * 16 + rh * 8;
                *(float2*)(C + rr * 128 + c0 + nb * 8) =
                    make_float2(c[rh * 2 + 0], c[rh * 2 + 1]);
            }
        }
    }
}

// ---------------------------------------------------------------------------
// Kernel 3b: merge partials -> masked scaled fp16 scores (per head)
// ---------------------------------------------------------------------------
__global__ __launch_bounds__(256) void merge_scores(int h) {
    int blk = blockIdx.x;          // 0..287 : tile p = blk>>3, slice = blk&7
    int p = blk >> 3;
    int sl = blk & 7;
    int bi = 0;
    while ((bi + 1) * (bi + 2) / 2 <= p) ++bi;
    int bj = p - bi * (bi + 1) / 2;

    const float* P0 = g_part[0][h][p] + sl * 16 * 128;
    const float* P1 = g_part[1][h][p] + sl * 16 * 128;
    long hb = (long)h * Tt * Tt;
    int trow0 = bi * 128 + sl * 16;

#pragma unroll
    for (int e = 0; e < 4; e++) {
        int i2 = e * 256 + threadIdx.x;
        int r = i2 >> 6;
        int cpair = (i2 & 63) * 2;
        float2 a = *(const float2*)(P0 + r * 128 + cpair);
        float2 b = *(const float2*)(P1 + r * 128 + cpair);
        int t = trow0 + r;
        int s = bj * 128 + cpair;
        float v0 = (s     < t) ? (a.x + b.x) * SCALE : 0.f;
        float v1 = (s + 1 < t) ? (a.y + b.y) * SCALE : 0.f;
        *(__half2*)(g_sh + hb + (long)t * Tt + s) =
            __halves2half2(__float2half_rn(v0), __float2half_rn(v1));
    }
}

// ---------------------------------------------------------------------------
// Kernel 4: out = scores @ V (per head, causal K)
// ---------------------------------------------------------------------------
__global__ __launch_bounds__(128, 2) void gemm2_out(float* __restrict__ O, int h) {
    extern __shared__ char dyn[];
    uint32_t s0 = smem_u32(dyn);
    int tid = threadIdx.x;
    int bn = blockIdx.x;          // d tile 0..63
    int bi = 7 - blockIdx.y;      // t tile, big-K first

    const __half* A = g_sh + (long)h * Tt * Tt + (long)bi * 128 * Tt;
    const __half* B = g_vt + ((long)h << 23) + (long)bn * 128 * Tt;

    float acc[4][8][4];
#pragma unroll
    for (int a = 0; a < 4; a++)
#pragma unroll
        for (int b = 0; b < 8; b++)
#pragma unroll
            for (int c = 0; c < 4; c++) acc[a][b][c] = 0.f;

    int nch = (bi + 1) * 2;
    gemm_run4(A, Tt, B, Tt, nch, s0, tid, acc, true, OPER_B);

    const int lane = tid & 31, wid = tid >> 5;
    const int wm = (wid & 1) * 64, wn = (wid >> 1) * 64;
    int tr0 = bi * 128 + wm + (lane >> 2);
    int dc0 = bn * 128 + wn + (lane & 3) * 2;
    long hb = ((long)h << 23);
#pragma unroll
    for (int mb = 0; mb < 4; mb++) {
#pragma unroll
        for (int nb = 0; nb < 8; nb++) {
            int dc = dc0 + nb * 8;
            float* c = acc[mb][nb];
#pragma unroll
            for (int rh = 0; rh < 2; rh++) {
                int rr = tr0 + mb * 16 + rh * 8;
                *(float2*)(O + hb + (long)rr * Dd + dc) =
                    make_float2(c[rh * 2 + 0], c[rh * 2 + 1]);
            }
        }
    }
}

__global__ void noop_kernel() {}

// ---------------------------------------------------------------------------
extern "C" void kernel_launch(void* const* d_in, const int* in_sizes, int n_in,
                              void* d_out, int out_size) {
    (void)in_sizes; (void)n_in; (void)out_size;
    const float* query = (const float*)d_in[0];
    const float* value = (const float*)d_in[1];
    float* out = (float*)d_out;

    const int SMEM_BYTES = NST * STAGE;   // 96 KB per CTA
    static cudaStream_t s_side[3] = {0, 0, 0};
    static cudaEvent_t ev_fork = 0;
    static cudaEvent_t ev_join[3] = {0, 0, 0};
    static int init_done = 0;
    if (!init_done) {
        cudaFuncSetAttribute(gemm1_partial, cudaFuncAttributeMaxDynamicSharedMemorySize, SMEM_BYTES);
        cudaFuncSetAttribute(gemm2_out,     cudaFuncAttributeMaxDynamicSharedMemorySize, SMEM_BYTES);
        for (int i = 0; i < 3; i++) {
            cudaStreamCreateWithFlags(&s_side[i], cudaStreamNonBlocking);
            cudaEventCreateWithFlags(&ev_join[i], cudaEventDisableTiming);
        }
        cudaEventCreateWithFlags(&ev_fork, cudaEventDisableTiming);
        init_done = 1;
    }

    // fork side streams off the main (capture) stream
    cudaEventRecord(ev_fork, 0);
    for (int i = 0; i < 3; i++)
        cudaStreamWaitEvent(s_side[i], ev_fork, 0);

    dim3 gt(Dd / 32, Tt / 32);
    dim3 g1(36, 2);
    dim3 g2(Dd / 128, Tt / 128);

    // per-head pipelines: head 0 on main stream, heads 1-3 on side streams
    for (int h = 0; h < Hh; h++) {
        cudaStream_t st = (h == 0) ? (cudaStream_t)0 : s_side[h - 1];
        rope_kernel<<<4096, 256, 0, st>>>(query, h);
        transpose_v<<<gt, 256, 0, st>>>(value, h);
        gemm1_partial<<<g1, 128, SMEM_BYTES, st>>>(h);
        merge_scores<<<288, 256, 0, st>>>(h);
        gemm2_out<<<g2, 128, SMEM_BYTES, st>>>(out, h);
    }

    // join side streams back into the main stream
    for (int i = 0; i < 3; i++) {
        cudaEventRecord(ev_join[i], s_side[i]);
        cudaStreamWaitEvent(0, ev_join[i], 0);
    }
    noop_kernel<<<1, 1>>>();
}

// round 16
// speedup vs baseline: 1.1369x; 1.0600x over previous
#include <cuda_runtime.h>
#include <cuda_fp16.h>
#include <cstdint>
#include <math.h>

#define Hh 4
#define Tt 1024
#define Dd 8192
#define SCALE 0.011048543456039806f  /* 1/sqrt(8192) */

// ---------------- scratch (static device arrays; no allocation) -------------
__device__ __half g_qh[(size_t)Hh * Tt * Dd];        // 64 MB  rope'd query fp16
__device__ __half g_vt[(size_t)Hh * Dd * Tt];        // 64 MB  V^T [h][d][s]
__device__ __half g_sh[(size_t)Hh * Tt * Tt];        // 8 MB   masked scores fp16
__device__ float  g_part[2][Hh][36][128 * 128];      // 18.9 MB gemm1 k-split partials

// ---------------- helpers (base-arch PTX only) ------------------------------
__device__ __forceinline__ uint32_t smem_u32(const void* p) {
    uint32_t a;
    asm("{ .reg .u64 t; cvta.to.shared.u64 t, %1; cvt.u32.u64 %0, t; }" : "=r"(a) : "l"(p));
    return a;
}
__device__ __forceinline__ void cp16(uint32_t dst, const void* src) {
    asm volatile("cp.async.cg.shared.global [%0], [%1], 16;" :: "r"(dst), "l"(src) : "memory");
}
#define CP_COMMIT asm volatile("cp.async.commit_group;" ::: "memory")
#define CP_WAIT1  asm volatile("cp.async.wait_group 1;" ::: "memory")

__device__ __forceinline__ void ldsm4(uint32_t& r0, uint32_t& r1, uint32_t& r2, uint32_t& r3,
                                      uint32_t a) {
    asm volatile("ldmatrix.sync.aligned.m8n8.x4.shared.b16 {%0,%1,%2,%3}, [%4];"
                 : "=r"(r0), "=r"(r1), "=r"(r2), "=r"(r3) : "r"(a));
}
__device__ __forceinline__ void mma16816(float* c,
                                         uint32_t a0, uint32_t a1, uint32_t a2, uint32_t a3,
                                         uint32_t b0, uint32_t b1) {
    asm volatile(
        "mma.sync.aligned.m16n8k16.row.col.f32.f16.f16.f32 "
        "{%0,%1,%2,%3},{%4,%5,%6,%7},{%8,%9},{%0,%1,%2,%3};"
        : "+f"(c[0]), "+f"(c[1]), "+f"(c[2]), "+f"(c[3])
        : "r"(a0), "r"(a1), "r"(a2), "r"(a3), "r"(b0), "r"(b1));
}

// 128B rows, XOR swizzle: conflict-free ldmatrix + cp.async
#define SWZ(row, cb) ((row) * 128 + ((cb) ^ (((row) & 7) << 4)))

// BK=64: operand tile = 128 rows x 128B = 16 KB
#define OPER_B   16384
#define STAGE    32768   /* A | B */
#define NST      3       /* 96 KB/CTA -> 2 CTA/SM */

// ---------------------------------------------------------------------------
// Kernel 1: bug-faithful ROPE -> fp16 (per head; 8 elems/thread, fast sincos)
// ---------------------------------------------------------------------------
__global__ void rope_kernel(const float* __restrict__ q, int h) {
    long idx = (long)blockIdx.x * 256 + threadIdx.x;   // 2^20 quad-pair idx/head
    int m4 = (int)(idx & (Dd / 8 - 1));                // 0..1023 (8-elem group)
    int t  = (int)(idx >> 10);                         // 0..1023
    int row = h * Tt + t;

    const float* qrow = q + ((long)row << 13);
    float4 v0 = *(const float4*)(qrow + 8 * m4);
    float4 v1 = *(const float4*)(qrow + 8 * m4 + 4);

    int m0   = 4 * m4;                                 // pair index base (4 pairs)
    int q2   = t & 1;
    int dsrc = (q2 << 12) + m0;
    int tsrc = ((h & 1) << 9) + (t >> 1);
    int h2   = h >> 1;
    const float* base = q + ((long)(2 * h2) << 23);
    float4 rA = *(const float4*)(base + (1L << 23) + (long)tsrc * Dd + dsrc); // j=0 src (negate)
    float4 rB = *(const float4*)(base + (long)tsrc * Dd + dsrc);              // j=1 src

    const float inv2pi = 0.15915494309189535f;
    const float twopi  = 6.283185307179586f;
    float tf = (float)t;
    float s[4], c[4];
#pragma unroll
    for (int i = 0; i < 4; i++) {
        float f = exp2f(-(float)(m0 + i) * (1.0f / 256.0f)) * inv2pi;
        float x = tf * f;
        float p = x - floorf(x);
        __sincosf(twopi * p, &s[i], &c[i]);
    }

    float o0 = v0.x * c[0] - rA.x * s[0];
    float o1 = v0.y * c[0] + rB.x * s[0];
    float o2 = v0.z * c[1] - rA.y * s[1];
    float o3 = v0.w * c[1] + rB.y * s[1];
    float o4 = v1.x * c[2] - rA.z * s[2];
    float o5 = v1.y * c[2] + rB.z * s[2];
    float o6 = v1.z * c[3] - rA.w * s[3];
    float o7 = v1.w * c[3] + rB.w * s[3];

    __half2 w0 = __halves2half2(__float2half_rn(o0), __float2half_rn(o1));
    __half2 w1 = __halves2half2(__float2half_rn(o2), __float2half_rn(o3));
    __half2 w2 = __halves2half2(__float2half_rn(o4), __float2half_rn(o5));
    __half2 w3 = __halves2half2(__float2half_rn(o6), __float2half_rn(o7));
    uint4 pk;
    pk.x = *(uint32_t*)&w0;
    pk.y = *(uint32_t*)&w1;
    pk.z = *(uint32_t*)&w2;
    pk.w = *(uint32_t*)&w3;
    *(uint4*)(g_qh + ((long)row << 13) + 8 * m4) = pk;
}

// ---------------------------------------------------------------------------
// Kernel 2: V transpose (per head) [s][d] fp32 -> V^T [d][s] fp16
// ---------------------------------------------------------------------------
__global__ __launch_bounds__(256) void transpose_v(const float* __restrict__ V, int h) {
    __shared__ float tile[32][33];
    int d0 = blockIdx.x * 32, s0 = blockIdx.y * 32;
    int lx = threadIdx.x & 31, ly = threadIdx.x >> 5;
    const float* src = V + ((long)h << 23);
#pragma unroll
    for (int r = 0; r < 4; r++)
        tile[ly + r * 8][lx] = src[(long)(s0 + ly + r * 8) * Dd + d0 + lx];
    __syncthreads();
    long ob = ((long)h << 23);
#pragma unroll
    for (int r = 0; r < 4; r++) {
        int d = d0 + ly + r * 8;
        g_vt[ob + (long)d * Tt + s0 + lx] = __float2half_rn(tile[lx][ly + r * 8]);
    }
}

// ---------------------------------------------------------------------------
// Shared GEMM core: CTA 128x128, 4 warps of 64x64, BK=64, 3-stage ring,
// register fragment double-buffering. b_region=OPER_B normally; 0 when the
// B tile is byte-identical to A (gemm1 diagonal tiles) -> B cp.async skipped.
// ---------------------------------------------------------------------------
__device__ __forceinline__ void ld_tile64(uint32_t sbase, const __half* g, long ld, int tid) {
#pragma unroll
    for (int i = 0; i < 8; i++) {
        int cid = i * 128 + tid;            // 0..1023
        int row = cid >> 3;
        int seg = cid & 7;
        cp16(sbase + SWZ(row, seg << 4), g + (long)row * ld + seg * 8);
    }
}

__device__ __forceinline__ void gemm_run4(
    const __half* __restrict__ A, long lda,
    const __half* __restrict__ B, long ldb,
    int nch, uint32_t s0, int tid, float acc[4][8][4], bool mma_on,
    uint32_t b_region)
{
    const int lane = tid & 31, wid = tid >> 5;
    const int wm = (wid & 1) * 64, wn = (wid >> 1) * 64;
    const bool load_b = (b_region != 0);

#pragma unroll
    for (int s = 0; s < NST - 1; s++) {
        uint32_t sb = s0 + s * STAGE;
        ld_tile64(sb, A + s * 64, lda, tid);
        if (load_b) ld_tile64(sb + OPER_B, B + s * 64, ldb, tid);
        CP_COMMIT;
    }

    const int arow = lane & 15;
    const int acb  = (lane >> 4) << 4;
    const int brow = (lane & 7) + ((lane >> 4) << 3);
    const int bcb  = ((lane >> 3) & 1) << 4;

    uint32_t af[2][4][4], bf[2][4][4];

    int st = 0, pf = NST - 1;
    for (int kc = 0; kc < nch; kc++) {
        CP_WAIT1;
        __syncthreads();

        int kn = kc + NST - 1;
        if (kn < nch) {
            uint32_t sbp = s0 + pf * STAGE;
            ld_tile64(sbp, A + kn * 64, lda, tid);
            if (load_b) ld_tile64(sbp + OPER_B, B + kn * 64, ldb, tid);
        }
        CP_COMMIT;

        uint32_t sb = s0 + st * STAGE;
        uint32_t sbB = sb + b_region;
        if (mma_on) {
#pragma unroll
            for (int mb = 0; mb < 4; mb++)
                ldsm4(af[0][mb][0], af[0][mb][1], af[0][mb][2], af[0][mb][3],
                      sb + SWZ(wm + mb * 16 + arow, acb));
#pragma unroll
            for (int nb = 0; nb < 4; nb++)
                ldsm4(bf[0][nb][0], bf[0][nb][1], bf[0][nb][2], bf[0][nb][3],
                      sbB + SWZ(wn + nb * 16 + brow, bcb));

#pragma unroll
            for (int kb = 0; kb < 4; kb++) {
                int cur = kb & 1, nxt = cur ^ 1;
                if (kb < 3) {
                    int cbk = (kb + 1) * 32;
#pragma unroll
                    for (int mb = 0; mb < 4; mb++)
                        ldsm4(af[nxt][mb][0], af[nxt][mb][1], af[nxt][mb][2], af[nxt][mb][3],
                              sb + SWZ(wm + mb * 16 + arow, cbk + acb));
#pragma unroll
                    for (int nb = 0; nb < 4; nb++)
                        ldsm4(bf[nxt][nb][0], bf[nxt][nb][1], bf[nxt][nb][2], bf[nxt][nb][3],
                              sbB + SWZ(wn + nb * 16 + brow, cbk + bcb));
                }
#pragma unroll
                for (int nb = 0; nb < 4; nb++) {
#pragma unroll
                    for (int mb = 0; mb < 4; mb++) {
                        mma16816(acc[mb][2 * nb],
                                 af[cur][mb][0], af[cur][mb][1], af[cur][mb][2], af[cur][mb][3],
                                 bf[cur][nb][0], bf[cur][nb][1]);
                        mma16816(acc[mb][2 * nb + 1],
                                 af[cur][mb][0], af[cur][mb][1], af[cur][mb][2], af[cur][mb][3],
                                 bf[cur][nb][2], bf[cur][nb][3]);
                    }
                }
            }
        }
        st = (st == NST - 1) ? 0 : st + 1;
        pf = (pf == NST - 1) ? 0 : pf + 1;
    }
}

// ---------------------------------------------------------------------------
// Kernel 3: gemm1 k-split partials (per head)
// ---------------------------------------------------------------------------
__global__ __launch_bounds__(128, 2) void gemm1_partial(int h) {
    extern __shared__ char dyn[];
    uint32_t s0 = smem_u32(dyn);
    int tid = threadIdx.x;
    int p  = blockIdx.x;   // 0..35 lower-tri tile
    int ks = blockIdx.y;   // k half
    int bi = 0;
    while ((bi + 1) * (bi + 2) / 2 <= p) ++bi;
    int bj = p - bi * (bi + 1) / 2;

    long qb = ((long)h << 23) + (long)ks * (Dd / 2);
    const __half* A = g_qh + qb + (long)bi * 128 * Dd;
    const __half* B = g_qh + qb + (long)bj * 128 * Dd;

    float acc[4][8][4];
#pragma unroll
    for (int a = 0; a < 4; a++)
#pragma unroll
        for (int b = 0; b < 8; b++)
#pragma unroll
            for (int c = 0; c < 4; c++) acc[a][b][c] = 0.f;

    const int lane = tid & 31, wid = tid >> 5;
    const int wm = (wid & 1) * 64, wn = (wid >> 1) * 64;
    bool mma_on = !(bi == bj && wn > wm);
    uint32_t b_region = (bi == bj) ? 0 : OPER_B;   // diag: B tile == A tile

    gemm_run4(A, Dd, B, Dd, Dd / 2 / 64, s0, tid, acc, mma_on, b_region);

    float* C = g_part[ks][h][p];
    int r0 = wm + (lane >> 2);
    int c0 = wn + (lane & 3) * 2;
#pragma unroll
    for (int mb = 0; mb < 4; mb++) {
#pragma unroll
        for (int nb = 0; nb < 8; nb++) {
            float* c = acc[mb][nb];
#pragma unroll
            for (int rh = 0; rh < 2; rh++) {
                int rr = r0 + mb * 16 + rh * 8;
                *(float2*)(C + rr * 128 + c0 + nb * 8) =
                    make_float2(c[rh * 2 + 0], c[rh * 2 + 1]);
            }
        }
    }
}

// ---------------------------------------------------------------------------
// Kernel 3b: merge partials -> masked scaled fp16 scores (per head)
// ---------------------------------------------------------------------------
__global__ __launch_bounds__(256) void merge_scores(int h) {
    int blk = blockIdx.x;          // 0..287 : tile p = blk>>3, slice = blk&7
    int p = blk >> 3;
    int sl = blk & 7;
    int bi = 0;
    while ((bi + 1) * (bi + 2) / 2 <= p) ++bi;
    int bj = p - bi * (bi + 1) / 2;

    const float* P0 = g_part[0][h][p] + sl * 16 * 128;
    const float* P1 = g_part[1][h][p] + sl * 16 * 128;
    long hb = (long)h * Tt * Tt;
    int trow0 = bi * 128 + sl * 16;

#pragma unroll
    for (int e = 0; e < 4; e++) {
        int i2 = e * 256 + threadIdx.x;
        int r = i2 >> 6;
        int cpair = (i2 & 63) * 2;
        float2 a = *(const float2*)(P0 + r * 128 + cpair);
        float2 b = *(const float2*)(P1 + r * 128 + cpair);
        int t = trow0 + r;
        int s = bj * 128 + cpair;
        float v0 = (s     < t) ? (a.x + b.x) * SCALE : 0.f;
        float v1 = (s + 1 < t) ? (a.y + b.y) * SCALE : 0.f;
        *(__half2*)(g_sh + hb + (long)t * Tt + s) =
            __halves2half2(__float2half_rn(v0), __float2half_rn(v1));
    }
}

// ---------------------------------------------------------------------------
// Kernel 4: out = scores @ V (per head, causal K)
// ---------------------------------------------------------------------------
__global__ __launch_bounds__(128, 2) void gemm2_out(float* __restrict__ O, int h) {
    extern __shared__ char dyn[];
    uint32_t s0 = smem_u32(dyn);
    int tid = threadIdx.x;
    int bn = blockIdx.x;          // d tile 0..63
    int bi = 7 - blockIdx.y;      // t tile, big-K first

    const __half* A = g_sh + (long)h * Tt * Tt + (long)bi * 128 * Tt;
    const __half* B = g_vt + ((long)h << 23) + (long)bn * 128 * Tt;

    float acc[4][8][4];
#pragma unroll
    for (int a = 0; a < 4; a++)
#pragma unroll
        for (int b = 0; b < 8; b++)
#pragma unroll
            for (int c = 0; c < 4; c++) acc[a][b][c] = 0.f;

    int nch = (bi + 1) * 2;
    gemm_run4(A, Tt, B, Tt, nch, s0, tid, acc, true, OPER_B);

    const int lane = tid & 31, wid = tid >> 5;
    const int wm = (wid & 1) * 64, wn = (wid >> 1) * 64;
    int tr0 = bi * 128 + wm + (lane >> 2);
    int dc0 = bn * 128 + wn + (lane & 3) * 2;
    long hb = ((long)h << 23);
#pragma unroll
    for (int mb = 0; mb < 4; mb++) {
#pragma unroll
        for (int nb = 0; nb < 8; nb++) {
            int dc = dc0 + nb * 8;
            float* c = acc[mb][nb];
#pragma unroll
            for (int rh = 0; rh < 2; rh++) {
                int rr = tr0 + mb * 16 + rh * 8;
                *(float2*)(O + hb + (long)rr * Dd + dc) =
                    make_float2(c[rh * 2 + 0], c[rh * 2 + 1]);
            }
        }
    }
}

__global__ void noop_kernel() {}

// ---------------------------------------------------------------------------
extern "C" void kernel_launch(void* const* d_in, const int* in_sizes, int n_in,
                              void* d_out, int out_size) {
    (void)in_sizes; (void)n_in; (void)out_size;
    const float* query = (const float*)d_in[0];
    const float* value = (const float*)d_in[1];
    float* out = (float*)d_out;

    const int SMEM_BYTES = NST * STAGE;   // 96 KB per CTA
    static cudaStream_t s_side[3] = {0, 0, 0};
    static cudaEvent_t ev_fork = 0;
    static cudaEvent_t evR[3];         // rope stagger chain (heads 0..2)
    static cudaEvent_t ev_join[3];
    static int init_done = 0;
    if (!init_done) {
        cudaFuncSetAttribute(gemm1_partial, cudaFuncAttributeMaxDynamicSharedMemorySize, SMEM_BYTES);
        cudaFuncSetAttribute(gemm2_out,     cudaFuncAttributeMaxDynamicSharedMemorySize, SMEM_BYTES);
        for (int i = 0; i < 3; i++) {
            cudaStreamCreateWithFlags(&s_side[i], cudaStreamNonBlocking);
            cudaEventCreateWithFlags(&evR[i], cudaEventDisableTiming);
            cudaEventCreateWithFlags(&ev_join[i], cudaEventDisableTiming);
        }
        cudaEventCreateWithFlags(&ev_fork, cudaEventDisableTiming);
        init_done = 1;
    }

    // fork side streams off the main (capture) stream
    cudaEventRecord(ev_fork, 0);
    for (int i = 0; i < 3; i++)
        cudaStreamWaitEvent(s_side[i], ev_fork, 0);

    dim3 gt(Dd / 32, Tt / 32);
    dim3 g1(36, 2);
    dim3 g2(Dd / 128, Tt / 128);

    cudaStream_t hstream[Hh] = {(cudaStream_t)0, s_side[0], s_side[1], s_side[2]};

    // per-head pipelines; ropes staggered so each runs alone at full BW while
    // previous heads' GEMMs own the tensor pipe. transpose_h sits after merge
    // (needed only by gemm2_h) filling DRAM under other heads' tensor phases.
    for (int h = 0; h < Hh; h++) {
        cudaStream_t st = hstream[h];
        if (h > 0) cudaStreamWaitEvent(st, evR[h - 1], 0);
        rope_kernel<<<4096, 256, 0, st>>>(query, h);
        if (h < 3) cudaEventRecord(evR[h], st);
        gemm1_partial<<<g1, 128, SMEM_BYTES, st>>>(h);
        merge_scores<<<288, 256, 0, st>>>(h);
        transpose_v<<<gt, 256, 0, st>>>(value, h);
        gemm2_out<<<g2, 128, SMEM_BYTES, st>>>(out, h);
    }

    // join side streams back into the main stream
    for (int i = 0; i < 3; i++) {
        cudaEventRecord(ev_join[i], s_side[i]);
        cudaStreamWaitEvent(0, ev_join[i], 0);
    }
    noop_kernel<<<1, 1>>>();
}